// round 12
// baseline (speedup 1.0000x reference)
#include <cuda_runtime.h>
#include <cuda_bf16.h>
#include <cstdint>
#include <cstddef>

#define N_NODES 50000
#define N_EDGES 800000
#define IN_DIM  100
#define HID     128
#define BN_EPS  1e-5f

#define SCAN_BLOCKS 196   // 196*256 = 50176 >= N_NODES

// ---------------------------------------------------------------------------
// Scratch (device globals; referenced ONLY inside device code)
// ---------------------------------------------------------------------------
__device__ int   g_deg   [N_NODES];
__device__ int   g_off   [N_NODES];
__device__ int   g_cursor[N_NODES];
__device__ int   g_bsum  [256];              // per-block scan totals
__device__ int   g_csr   [N_EDGES];          // src ids grouped by dst
__device__ float g_yl[N_NODES * HID];        // A @ W_l  (to be gathered)
__device__ float g_yr[N_NODES * HID];        // A @ W_r + b (root path)
__device__ float g_z [N_NODES * HID];        // layer0 pre-BN
__device__ float g_z2[N_NODES * HID];        // layer1 pre-BN
__device__ float g_stats[512];               // [L*256 + {sum[128], sumsq[128]}]

// ---------------------------------------------------------------------------
// Zero small accumulators (part of the graph, every replay)
// ---------------------------------------------------------------------------
__global__ void zero_small() {
    int i = blockIdx.x * blockDim.x + threadIdx.x;
    if (i < N_NODES) g_deg[i] = 0;
    if (i < 512)     g_stats[i] = 0.f;
}

// ---------------------------------------------------------------------------
// CSR build: histogram -> parallel 3-phase scan -> cursor fill
// ---------------------------------------------------------------------------
__global__ void csr_hist(const int* __restrict__ ei) {
    int e = blockIdx.x * blockDim.x + threadIdx.x;
    if (e >= N_EDGES) return;
    atomicAdd(&g_deg[ei[N_EDGES + e]], 1);
}

// Phase 1: per-block exclusive scan of deg (coalesced), block totals out.
__global__ void __launch_bounds__(256) scan_p1() {
    __shared__ int sh[256];
    int t = threadIdx.x;
    int i = blockIdx.x * 256 + t;
    int d = (i < N_NODES) ? g_deg[i] : 0;
    sh[t] = d;
    __syncthreads();
    #pragma unroll
    for (int s = 1; s < 256; s <<= 1) {
        int v = (t >= s) ? sh[t - s] : 0;
        __syncthreads();
        sh[t] += v;
        __syncthreads();
    }
    if (i < N_NODES) g_off[i] = sh[t] - d;     // exclusive within block
    if (t == 255) g_bsum[blockIdx.x] = sh[255];
}

// Phase 2: single-block exclusive scan of the 196 block totals.
__global__ void __launch_bounds__(256) scan_p2() {
    __shared__ int sh[256];
    int t = threadIdx.x;
    int d = (t < SCAN_BLOCKS) ? g_bsum[t] : 0;
    sh[t] = d;
    __syncthreads();
    #pragma unroll
    for (int s = 1; s < 256; s <<= 1) {
        int v = (t >= s) ? sh[t - s] : 0;
        __syncthreads();
        sh[t] += v;
        __syncthreads();
    }
    if (t < SCAN_BLOCKS) g_bsum[t] = sh[t] - d;  // exclusive
}

// Phase 3: add block base, init cursor.
__global__ void __launch_bounds__(256) scan_p3() {
    int i = blockIdx.x * 256 + threadIdx.x;
    if (i >= N_NODES) return;
    int o = g_off[i] + g_bsum[blockIdx.x];
    g_off[i]    = o;
    g_cursor[i] = o;
}

__global__ void csr_fill(const int* __restrict__ ei) {
    int e = blockIdx.x * blockDim.x + threadIdx.x;
    if (e >= N_EDGES) return;
    int src = ei[e];
    int dst = ei[N_EDGES + e];
    int pos = atomicAdd(&g_cursor[dst], 1);
    g_csr[pos] = src;
}

// ---------------------------------------------------------------------------
// GEMM: Out[n, 0:128] = A[n, 0:K] @ W   (f32x2 packed FMA, 8x8 thread tile)
// Block tile: 128 nodes x 128 cols, 256 threads, K chunks of 32.
// blockIdx.y: 0 -> W_l -> g_yl (no bias), 1 -> W_r -> g_yr (+bias)
// L=0: A = x (arg).  L=1: A = relu(BN0(g_z)) with affine computed in-kernel
// from g_stats[0..255] + gamma0/beta0.
// ---------------------------------------------------------------------------
template <int L>
__global__ void __launch_bounds__(256) gemm128(
    const float* __restrict__ Xin,
    const float* __restrict__ Wl, const float* __restrict__ Wr,
    const float* __restrict__ bias,
    const float* __restrict__ gamma, const float* __restrict__ beta)
{
    constexpr int K = (L == 0) ? IN_DIM : HID;
    const float* __restrict__ A   = (L == 0) ? Xin : g_z;
    const float* __restrict__ W   = blockIdx.y ? Wr   : Wl;
    float* __restrict__       Out = blockIdx.y ? g_yr : g_yl;

    __shared__ __align__(16) float As[32][129];  // [k][node]
    __shared__ __align__(16) float Ws[32][128];  // [k][col]
    __shared__ float aff[256];                   // BN0 scale/shift (L==1)

    const int tid = threadIdx.x;
    const int nb  = blockIdx.x * 128;
    const int c8  = (tid & 15) * 8;   // 8 contiguous output cols
    const int r8  = (tid >> 4) * 8;   // 8 rows

    if (L == 1) {
        if (tid < 128) {
            float s = g_stats[tid];
            float q = g_stats[128 + tid];
            float mean = s * (1.0f / N_NODES);
            float var  = q * (1.0f / N_NODES) - mean * mean;
            float sc   = gamma[tid] * rsqrtf(var + BN_EPS);
            aff[tid]       = sc;
            aff[128 + tid] = beta[tid] - mean * sc;
        }
        __syncthreads();
    }

    unsigned long long acc2[8][4];
    #pragma unroll
    for (int i = 0; i < 8; i++)
        #pragma unroll
        for (int j = 0; j < 4; j++) acc2[i][j] = 0ull;

    for (int k0 = 0; k0 < K; k0 += 32) {
        #pragma unroll
        for (int t = tid; t < 32 * 128; t += 256) {
            int kk = t >> 7, c = t & 127;
            int k = k0 + kk;
            Ws[kk][c] = (k < K) ? W[(size_t)k * 128 + c] : 0.f;
        }
        #pragma unroll
        for (int t = tid; t < 128 * 32; t += 256) {
            int ni = t >> 5, kk = t & 31;
            int n = nb + ni, k = k0 + kk;
            float a = 0.f;
            if (n < N_NODES && k < K) {
                a = A[(size_t)n * K + k];
                if (L == 1) a = fmaxf(fmaf(a, aff[k], aff[128 + k]), 0.f);
            }
            As[kk][ni] = a;
        }
        __syncthreads();

        #pragma unroll
        for (int kk = 0; kk < 32; kk++) {
            ulonglong2 w01 = *reinterpret_cast<const ulonglong2*>(&Ws[kk][c8]);
            ulonglong2 w23 = *reinterpret_cast<const ulonglong2*>(&Ws[kk][c8 + 4]);
            #pragma unroll
            for (int i = 0; i < 8; i++) {
                float a = As[kk][r8 + i];
                unsigned long long a2;
                asm("mov.b64 %0, {%1, %1};" : "=l"(a2) : "f"(a));
                asm("fma.rn.f32x2 %0, %1, %2, %0;" : "+l"(acc2[i][0]) : "l"(a2), "l"(w01.x));
                asm("fma.rn.f32x2 %0, %1, %2, %0;" : "+l"(acc2[i][1]) : "l"(a2), "l"(w01.y));
                asm("fma.rn.f32x2 %0, %1, %2, %0;" : "+l"(acc2[i][2]) : "l"(a2), "l"(w23.x));
                asm("fma.rn.f32x2 %0, %1, %2, %0;" : "+l"(acc2[i][3]) : "l"(a2), "l"(w23.y));
            }
        }
        __syncthreads();
    }

    float4 bv0 = make_float4(0.f, 0.f, 0.f, 0.f);
    float4 bv1 = make_float4(0.f, 0.f, 0.f, 0.f);
    if (blockIdx.y) {
        bv0 = *reinterpret_cast<const float4*>(&bias[c8]);
        bv1 = *reinterpret_cast<const float4*>(&bias[c8 + 4]);
    }
    #pragma unroll
    for (int i = 0; i < 8; i++) {
        int n = nb + r8 + i;
        if (n < N_NODES) {
            float2 p0 = *reinterpret_cast<float2*>(&acc2[i][0]);
            float2 p1 = *reinterpret_cast<float2*>(&acc2[i][1]);
            float2 p2 = *reinterpret_cast<float2*>(&acc2[i][2]);
            float2 p3 = *reinterpret_cast<float2*>(&acc2[i][3]);
            float4 o0 = make_float4(p0.x + bv0.x, p0.y + bv0.y, p1.x + bv0.z, p1.y + bv0.w);
            float4 o1 = make_float4(p2.x + bv1.x, p2.y + bv1.y, p3.x + bv1.z, p3.y + bv1.w);
            *reinterpret_cast<float4*>(&Out[(size_t)n * 128 + c8])     = o0;
            *reinterpret_cast<float4*>(&Out[(size_t)n * 128 + c8 + 4]) = o1;
        }
    }
}

// ---------------------------------------------------------------------------
// Gather: z[n,f] = (sum_{j in N(n)} yl[j,f]) / max(deg,1) + yr[n,f]
// One warp per node; lane owns 16B (float4); unroll 8 for MLP.
// ---------------------------------------------------------------------------
template <int L>
__global__ void __launch_bounds__(256) gather() {
    int node = (blockIdx.x * 256 + threadIdx.x) >> 5;
    if (node >= N_NODES) return;
    int lane = threadIdx.x & 31;
    int off  = g_off[node];
    int deg  = g_deg[node];
    float* __restrict__ Z = (L == 0) ? g_z : g_z2;

    float4 s[8];
    #pragma unroll
    for (int j = 0; j < 8; j++) s[j] = make_float4(0.f, 0.f, 0.f, 0.f);

    const size_t fo = (size_t)lane * 4;
    int e = 0;
    for (; e + 8 <= deg; e += 8) {
        int idx[8];
        #pragma unroll
        for (int j = 0; j < 8; j++) idx[j] = g_csr[off + e + j];
        #pragma unroll
        for (int j = 0; j < 8; j++) {
            float4 v = *reinterpret_cast<const float4*>(&g_yl[(size_t)idx[j] * 128 + fo]);
            s[j].x += v.x; s[j].y += v.y; s[j].z += v.z; s[j].w += v.w;
        }
    }
    for (; e < deg; e++) {
        int j = g_csr[off + e];
        float4 v = *reinterpret_cast<const float4*>(&g_yl[(size_t)j * 128 + fo]);
        s[0].x += v.x; s[0].y += v.y; s[0].z += v.z; s[0].w += v.w;
    }

    float4 t0, t1;
    t0.x = (s[0].x + s[1].x) + (s[2].x + s[3].x);
    t0.y = (s[0].y + s[1].y) + (s[2].y + s[3].y);
    t0.z = (s[0].z + s[1].z) + (s[2].z + s[3].z);
    t0.w = (s[0].w + s[1].w) + (s[2].w + s[3].w);
    t1.x = (s[4].x + s[5].x) + (s[6].x + s[7].x);
    t1.y = (s[4].y + s[5].y) + (s[6].y + s[7].y);
    t1.z = (s[4].z + s[5].z) + (s[6].z + s[7].z);
    t1.w = (s[4].w + s[5].w) + (s[6].w + s[7].w);

    float inv = 1.f / fmaxf((float)deg, 1.f);
    float4 r = *reinterpret_cast<const float4*>(&g_yr[(size_t)node * 128 + fo]);
    float4 o;
    o.x = fmaf(t0.x + t1.x, inv, r.x);
    o.y = fmaf(t0.y + t1.y, inv, r.y);
    o.z = fmaf(t0.z + t1.z, inv, r.z);
    o.w = fmaf(t0.w + t1.w, inv, r.w);
    *reinterpret_cast<float4*>(&Z[(size_t)node * 128 + fo]) = o;
}

// ---------------------------------------------------------------------------
// BN stats: float4 per lane, coalesced rows, smem block-reduce, one global
// atomic per thread at the end.
// ---------------------------------------------------------------------------
template <int L>
__global__ void __launch_bounds__(256) bn_stats() {
    const float* __restrict__ Z = (L == 0) ? g_z : g_z2;
    __shared__ float sm[256];          // [0:128) sum, [128:256) sumsq
    int t    = threadIdx.x;
    int lane = t & 31;
    int warp = t >> 5;                 // 8 warps -> 8 rows per iter
    int c4   = lane * 4;
    sm[t] = 0.f;
    __syncthreads();

    float4 s = make_float4(0.f, 0.f, 0.f, 0.f);
    float4 q = make_float4(0.f, 0.f, 0.f, 0.f);
    int rstep = gridDim.x * 8;
    for (int r = blockIdx.x * 8 + warp; r < N_NODES; r += rstep) {
        float4 v = *reinterpret_cast<const float4*>(&Z[(size_t)r * HID + c4]);
        s.x += v.x; s.y += v.y; s.z += v.z; s.w += v.w;
        q.x = fmaf(v.x, v.x, q.x); q.y = fmaf(v.y, v.y, q.y);
        q.z = fmaf(v.z, v.z, q.z); q.w = fmaf(v.w, v.w, q.w);
    }
    atomicAdd(&sm[c4 + 0], s.x); atomicAdd(&sm[c4 + 1], s.y);
    atomicAdd(&sm[c4 + 2], s.z); atomicAdd(&sm[c4 + 3], s.w);
    atomicAdd(&sm[128 + c4 + 0], q.x); atomicAdd(&sm[128 + c4 + 1], q.y);
    atomicAdd(&sm[128 + c4 + 2], q.z); atomicAdd(&sm[128 + c4 + 3], q.w);
    __syncthreads();
    atomicAdd(&g_stats[L * 256 + t], sm[t]);
}

// ---------------------------------------------------------------------------
// Output: out = BN1(z2), affine computed in-kernel from g_stats[256..511].
// ---------------------------------------------------------------------------
__global__ void __launch_bounds__(256) apply_out(
    float* __restrict__ out,
    const float* __restrict__ gamma, const float* __restrict__ beta)
{
    __shared__ float aff[256];
    int t = threadIdx.x;
    if (t < 128) {
        float s = g_stats[256 + t];
        float q = g_stats[384 + t];
        float mean = s * (1.0f / N_NODES);
        float var  = q * (1.0f / N_NODES) - mean * mean;
        float sc   = gamma[t] * rsqrtf(var + BN_EPS);
        aff[t]       = sc;
        aff[128 + t] = beta[t] - mean * sc;
    }
    __syncthreads();

    int i0 = blockIdx.x * 256 + t;
    int stride = gridDim.x * 256;
    const int total4 = N_NODES * HID / 4;
    for (int i = i0; i < total4; i += stride) {
        int c4 = (i & 31) * 4;
        float4 v = *reinterpret_cast<const float4*>(&g_z2[(size_t)i * 4]);
        float4 o;
        o.x = fmaf(v.x, aff[c4 + 0], aff[128 + c4 + 0]);
        o.y = fmaf(v.y, aff[c4 + 1], aff[128 + c4 + 1]);
        o.z = fmaf(v.z, aff[c4 + 2], aff[128 + c4 + 2]);
        o.w = fmaf(v.w, aff[c4 + 3], aff[128 + c4 + 3]);
        *reinterpret_cast<float4*>(&out[(size_t)i * 4]) = o;
    }
}

// ---------------------------------------------------------------------------
// Launch
// Inputs: 0:x 1:edge_index 2:W_l0 3:b_l0 4:W_r0 5:gamma0 6:beta0
//         7:W_l1 8:b_l1 9:W_r1 10:gamma1 11:beta1
// ---------------------------------------------------------------------------
extern "C" void kernel_launch(void* const* d_in, const int* in_sizes, int n_in,
                              void* d_out, int out_size) {
    const float* x      = (const float*)d_in[0];
    const int*   ei     = (const int*)  d_in[1];
    const float* W_l0   = (const float*)d_in[2];
    const float* b_l0   = (const float*)d_in[3];
    const float* W_r0   = (const float*)d_in[4];
    const float* gamma0 = (const float*)d_in[5];
    const float* beta0  = (const float*)d_in[6];
    const float* W_l1   = (const float*)d_in[7];
    const float* b_l1   = (const float*)d_in[8];
    const float* W_r1   = (const float*)d_in[9];
    const float* gamma1 = (const float*)d_in[10];
    const float* beta1  = (const float*)d_in[11];
    float* out = (float*)d_out;

    const int edge_blocks   = (N_EDGES + 255) / 256;
    const int gemm_blocks   = (N_NODES + 127) / 128;
    const int gather_blocks = (N_NODES * 32 + 255) / 256;   // warp per node

    zero_small<<<(N_NODES + 255) / 256, 256>>>();
    csr_hist<<<edge_blocks, 256>>>(ei);
    scan_p1<<<SCAN_BLOCKS, 256>>>();
    scan_p2<<<1, 256>>>();
    scan_p3<<<SCAN_BLOCKS, 256>>>();
    csr_fill<<<edge_blocks, 256>>>(ei);

    // Layer 0
    gemm128<0><<<dim3(gemm_blocks, 2), 256>>>(x, W_l0, W_r0, b_l0, nullptr, nullptr);
    gather<0><<<gather_blocks, 256>>>();
    bn_stats<0><<<512, 256>>>();

    // Layer 1 (BN0 affine computed in-kernel; BN0+ReLU fused into A-load)
    gemm128<1><<<dim3(gemm_blocks, 2), 256>>>(x, W_l1, W_r1, b_l1, gamma0, beta0);
    gather<1><<<gather_blocks, 256>>>();
    bn_stats<1><<<512, 256>>>();
    apply_out<<<2048, 256>>>(out, gamma1, beta1);
}

// round 13
// speedup vs baseline: 1.4554x; 1.4554x over previous
#include <cuda_runtime.h>
#include <cuda_bf16.h>
#include <cstdint>
#include <cstddef>

#define N_NODES 50000
#define N_EDGES 800000
#define IN_DIM  100
#define HID     128
#define BN_EPS  1e-5f

#define SCAN_BLOCKS 196   // 196*256 = 50176 >= N_NODES

// ---------------------------------------------------------------------------
// Scratch (device globals; referenced ONLY inside device code)
// ---------------------------------------------------------------------------
__device__ int   g_deg   [N_NODES];
__device__ int   g_off   [N_NODES];
__device__ int   g_cursor[N_NODES];
__device__ int   g_bsum  [256];              // per-block scan totals
__device__ int   g_csr   [N_EDGES];          // src ids grouped by dst
__device__ float g_yl[N_NODES * HID];        // A @ W_l  (to be gathered)
__device__ float g_yr[N_NODES * HID];        // A @ W_r + b (root path)
__device__ float g_z [N_NODES * HID];        // layer0 pre-BN
__device__ float g_z2[N_NODES * HID];        // layer1 pre-BN
__device__ float g_stats[512];               // [L*256 + {sum[128], sumsq[128]}]

// ---------------------------------------------------------------------------
// Zero small accumulators (part of the graph, every replay)
// ---------------------------------------------------------------------------
__global__ void zero_small() {
    int i = blockIdx.x * blockDim.x + threadIdx.x;
    if (i < N_NODES) g_deg[i] = 0;
    if (i < 512)     g_stats[i] = 0.f;
}

// ---------------------------------------------------------------------------
// CSR build: histogram -> 2-phase scan -> cursor fill
// ---------------------------------------------------------------------------
__global__ void csr_hist(const int* __restrict__ ei) {
    int e = blockIdx.x * blockDim.x + threadIdx.x;
    if (e >= N_EDGES) return;
    atomicAdd(&g_deg[ei[N_EDGES + e]], 1);
}

// Phase 1: per-block exclusive scan of deg (coalesced), block totals out.
__global__ void __launch_bounds__(256) scan_p1() {
    __shared__ int sh[256];
    int t = threadIdx.x;
    int i = blockIdx.x * 256 + t;
    int d = (i < N_NODES) ? g_deg[i] : 0;
    sh[t] = d;
    __syncthreads();
    #pragma unroll
    for (int s = 1; s < 256; s <<= 1) {
        int v = (t >= s) ? sh[t - s] : 0;
        __syncthreads();
        sh[t] += v;
        __syncthreads();
    }
    if (i < N_NODES) g_off[i] = sh[t] - d;     // exclusive within block
    if (t == 255) g_bsum[blockIdx.x] = sh[255];
}

// Phase 2+3 merged: every block re-scans the 196 block totals in smem,
// then applies its own base. (196 ints: trivial, removes the serial
// single-block launch bubble.)
__global__ void __launch_bounds__(256) scan_p23() {
    __shared__ int sh[256];
    int t = threadIdx.x;
    int d = (t < SCAN_BLOCKS) ? g_bsum[t] : 0;
    sh[t] = d;
    __syncthreads();
    #pragma unroll
    for (int s = 1; s < 256; s <<= 1) {
        int v = (t >= s) ? sh[t - s] : 0;
        __syncthreads();
        sh[t] += v;
        __syncthreads();
    }
    // exclusive base for this block
    int base = (blockIdx.x == 0) ? 0 : sh[blockIdx.x - 1];
    int i = blockIdx.x * 256 + t;
    if (i >= N_NODES) return;
    int o = g_off[i] + base;
    g_off[i]    = o;
    g_cursor[i] = o;
}

__global__ void csr_fill(const int* __restrict__ ei) {
    int e = blockIdx.x * blockDim.x + threadIdx.x;
    if (e >= N_EDGES) return;
    int src = ei[e];
    int dst = ei[N_EDGES + e];
    int pos = atomicAdd(&g_cursor[dst], 1);
    g_csr[pos] = src;
}

// ---------------------------------------------------------------------------
// GEMM: Out[n, 0:128] = A[n, 0:K] @ W   (f32x2 packed FMA, 8x8 thread tile)
// Block tile: 128 nodes x 128 cols, 256 threads, K chunks of 32.
// blockIdx.y: 0 -> W_l -> g_yl (no bias), 1 -> W_r -> g_yr (+bias)
// L=0: A = x (arg).  L=1: A = relu(BN0(g_z)) with affine computed in-kernel
// from g_stats[0..255] + gamma0/beta0.
// ---------------------------------------------------------------------------
template <int L>
__global__ void __launch_bounds__(256) gemm128(
    const float* __restrict__ Xin,
    const float* __restrict__ Wl, const float* __restrict__ Wr,
    const float* __restrict__ bias,
    const float* __restrict__ gamma, const float* __restrict__ beta)
{
    constexpr int K = (L == 0) ? IN_DIM : HID;
    const float* __restrict__ A   = (L == 0) ? Xin : g_z;
    const float* __restrict__ W   = blockIdx.y ? Wr   : Wl;
    float* __restrict__       Out = blockIdx.y ? g_yr : g_yl;

    __shared__ __align__(16) float As[32][129];  // [k][node]
    __shared__ __align__(16) float Ws[32][128];  // [k][col]
    __shared__ float aff[256];                   // BN0 scale/shift (L==1)

    const int tid = threadIdx.x;
    const int nb  = blockIdx.x * 128;
    const int c8  = (tid & 15) * 8;   // 8 contiguous output cols
    const int r8  = (tid >> 4) * 8;   // 8 rows

    if (L == 1) {
        if (tid < 128) {
            float s = g_stats[tid];
            float q = g_stats[128 + tid];
            float mean = s * (1.0f / N_NODES);
            float var  = q * (1.0f / N_NODES) - mean * mean;
            float sc   = gamma[tid] * rsqrtf(var + BN_EPS);
            aff[tid]       = sc;
            aff[128 + tid] = beta[tid] - mean * sc;
        }
        __syncthreads();
    }

    unsigned long long acc2[8][4];
    #pragma unroll
    for (int i = 0; i < 8; i++)
        #pragma unroll
        for (int j = 0; j < 4; j++) acc2[i][j] = 0ull;

    for (int k0 = 0; k0 < K; k0 += 32) {
        #pragma unroll
        for (int t = tid; t < 32 * 128; t += 256) {
            int kk = t >> 7, c = t & 127;
            int k = k0 + kk;
            Ws[kk][c] = (k < K) ? W[(size_t)k * 128 + c] : 0.f;
        }
        #pragma unroll
        for (int t = tid; t < 128 * 32; t += 256) {
            int ni = t >> 5, kk = t & 31;
            int n = nb + ni, k = k0 + kk;
            float a = 0.f;
            if (n < N_NODES && k < K) {
                a = A[(size_t)n * K + k];
                if (L == 1) a = fmaxf(fmaf(a, aff[k], aff[128 + k]), 0.f);
            }
            As[kk][ni] = a;
        }
        __syncthreads();

        #pragma unroll
        for (int kk = 0; kk < 32; kk++) {
            ulonglong2 w01 = *reinterpret_cast<const ulonglong2*>(&Ws[kk][c8]);
            ulonglong2 w23 = *reinterpret_cast<const ulonglong2*>(&Ws[kk][c8 + 4]);
            #pragma unroll
            for (int i = 0; i < 8; i++) {
                float a = As[kk][r8 + i];
                unsigned long long a2;
                asm("mov.b64 %0, {%1, %1};" : "=l"(a2) : "f"(a));
                asm("fma.rn.f32x2 %0, %1, %2, %0;" : "+l"(acc2[i][0]) : "l"(a2), "l"(w01.x));
                asm("fma.rn.f32x2 %0, %1, %2, %0;" : "+l"(acc2[i][1]) : "l"(a2), "l"(w01.y));
                asm("fma.rn.f32x2 %0, %1, %2, %0;" : "+l"(acc2[i][2]) : "l"(a2), "l"(w23.x));
                asm("fma.rn.f32x2 %0, %1, %2, %0;" : "+l"(acc2[i][3]) : "l"(a2), "l"(w23.y));
            }
        }
        __syncthreads();
    }

    float4 bv0 = make_float4(0.f, 0.f, 0.f, 0.f);
    float4 bv1 = make_float4(0.f, 0.f, 0.f, 0.f);
    if (blockIdx.y) {
        bv0 = *reinterpret_cast<const float4*>(&bias[c8]);
        bv1 = *reinterpret_cast<const float4*>(&bias[c8 + 4]);
    }
    #pragma unroll
    for (int i = 0; i < 8; i++) {
        int n = nb + r8 + i;
        if (n < N_NODES) {
            float2 p0 = *reinterpret_cast<float2*>(&acc2[i][0]);
            float2 p1 = *reinterpret_cast<float2*>(&acc2[i][1]);
            float2 p2 = *reinterpret_cast<float2*>(&acc2[i][2]);
            float2 p3 = *reinterpret_cast<float2*>(&acc2[i][3]);
            float4 o0 = make_float4(p0.x + bv0.x, p0.y + bv0.y, p1.x + bv0.z, p1.y + bv0.w);
            float4 o1 = make_float4(p2.x + bv1.x, p2.y + bv1.y, p3.x + bv1.z, p3.y + bv1.w);
            *reinterpret_cast<float4*>(&Out[(size_t)n * 128 + c8])     = o0;
            *reinterpret_cast<float4*>(&Out[(size_t)n * 128 + c8 + 4]) = o1;
        }
    }
}

// ---------------------------------------------------------------------------
// Gather + fused BN stats:
//   z[n,f] = (sum_{j in N(n)} yl[j,f]) / max(deg,1) + yr[n,f]
//   g_stats[L] += per-column {sum, sumsq} of z (block-reduced, then atomics)
// One warp per node (8 nodes / 256-thread block); lane owns 16B (float4).
// ---------------------------------------------------------------------------
template <int L>
__global__ void __launch_bounds__(256) gather_stats() {
    __shared__ float ssum[8][128];
    __shared__ float ssq [8][128];

    int t    = threadIdx.x;
    int warp = t >> 5;
    int lane = t & 31;
    int node = blockIdx.x * 8 + warp;
    bool live = (node < N_NODES);
    float* __restrict__ Z = (L == 0) ? g_z : g_z2;

    float4 o = make_float4(0.f, 0.f, 0.f, 0.f);
    const size_t fo = (size_t)lane * 4;

    if (live) {
        int off = g_off[node];
        int deg = g_deg[node];

        float4 s[8];
        #pragma unroll
        for (int j = 0; j < 8; j++) s[j] = make_float4(0.f, 0.f, 0.f, 0.f);

        int e = 0;
        for (; e + 8 <= deg; e += 8) {
            int idx[8];
            #pragma unroll
            for (int j = 0; j < 8; j++) idx[j] = g_csr[off + e + j];
            #pragma unroll
            for (int j = 0; j < 8; j++) {
                float4 v = *reinterpret_cast<const float4*>(&g_yl[(size_t)idx[j] * 128 + fo]);
                s[j].x += v.x; s[j].y += v.y; s[j].z += v.z; s[j].w += v.w;
            }
        }
        for (; e < deg; e++) {
            int j = g_csr[off + e];
            float4 v = *reinterpret_cast<const float4*>(&g_yl[(size_t)j * 128 + fo]);
            s[0].x += v.x; s[0].y += v.y; s[0].z += v.z; s[0].w += v.w;
        }

        float4 t0, t1;
        t0.x = (s[0].x + s[1].x) + (s[2].x + s[3].x);
        t0.y = (s[0].y + s[1].y) + (s[2].y + s[3].y);
        t0.z = (s[0].z + s[1].z) + (s[2].z + s[3].z);
        t0.w = (s[0].w + s[1].w) + (s[2].w + s[3].w);
        t1.x = (s[4].x + s[5].x) + (s[6].x + s[7].x);
        t1.y = (s[4].y + s[5].y) + (s[6].y + s[7].y);
        t1.z = (s[4].z + s[5].z) + (s[6].z + s[7].z);
        t1.w = (s[4].w + s[5].w) + (s[6].w + s[7].w);

        float inv = 1.f / fmaxf((float)deg, 1.f);
        float4 r = *reinterpret_cast<const float4*>(&g_yr[(size_t)node * 128 + fo]);
        o.x = fmaf(t0.x + t1.x, inv, r.x);
        o.y = fmaf(t0.y + t1.y, inv, r.y);
        o.z = fmaf(t0.z + t1.z, inv, r.z);
        o.w = fmaf(t0.w + t1.w, inv, r.w);
        *reinterpret_cast<float4*>(&Z[(size_t)node * 128 + fo]) = o;
    }

    // per-warp stats rows (dead warps write zeros)
    int c4 = lane * 4;
    ssum[warp][c4 + 0] = o.x;  ssum[warp][c4 + 1] = o.y;
    ssum[warp][c4 + 2] = o.z;  ssum[warp][c4 + 3] = o.w;
    ssq [warp][c4 + 0] = o.x * o.x;  ssq[warp][c4 + 1] = o.y * o.y;
    ssq [warp][c4 + 2] = o.z * o.z;  ssq[warp][c4 + 3] = o.w * o.w;
    __syncthreads();

    // 256 threads reduce 8 rows: t = kind*128 + col
    int col  = t & 127;
    int kind = t >> 7;                 // 0 = sum, 1 = sumsq
    const float (*src)[128] = kind ? ssq : ssum;
    float tot = 0.f;
    #pragma unroll
    for (int w = 0; w < 8; w++) tot += src[w][col];
    atomicAdd(&g_stats[L * 256 + kind * 128 + col], tot);
}

// ---------------------------------------------------------------------------
// Output: out = BN1(z2), affine computed in-kernel from g_stats[256..511].
// ---------------------------------------------------------------------------
__global__ void __launch_bounds__(256) apply_out(
    float* __restrict__ out,
    const float* __restrict__ gamma, const float* __restrict__ beta)
{
    __shared__ float aff[256];
    int t = threadIdx.x;
    if (t < 128) {
        float s = g_stats[256 + t];
        float q = g_stats[384 + t];
        float mean = s * (1.0f / N_NODES);
        float var  = q * (1.0f / N_NODES) - mean * mean;
        float sc   = gamma[t] * rsqrtf(var + BN_EPS);
        aff[t]       = sc;
        aff[128 + t] = beta[t] - mean * sc;
    }
    __syncthreads();

    int i0 = blockIdx.x * 256 + t;
    int stride = gridDim.x * 256;
    const int total4 = N_NODES * HID / 4;
    for (int i = i0; i < total4; i += stride) {
        int c4 = (i & 31) * 4;
        float4 v = *reinterpret_cast<const float4*>(&g_z2[(size_t)i * 4]);
        float4 o;
        o.x = fmaf(v.x, aff[c4 + 0], aff[128 + c4 + 0]);
        o.y = fmaf(v.y, aff[c4 + 1], aff[128 + c4 + 1]);
        o.z = fmaf(v.z, aff[c4 + 2], aff[128 + c4 + 2]);
        o.w = fmaf(v.w, aff[c4 + 3], aff[128 + c4 + 3]);
        *reinterpret_cast<float4*>(&out[(size_t)i * 4]) = o;
    }
}

// ---------------------------------------------------------------------------
// Launch
// Inputs: 0:x 1:edge_index 2:W_l0 3:b_l0 4:W_r0 5:gamma0 6:beta0
//         7:W_l1 8:b_l1 9:W_r1 10:gamma1 11:beta1
// Launch order puts gemm128<0> 6th so ncu (-s 5 -c 1) profiles it.
// ---------------------------------------------------------------------------
extern "C" void kernel_launch(void* const* d_in, const int* in_sizes, int n_in,
                              void* d_out, int out_size) {
    const float* x      = (const float*)d_in[0];
    const int*   ei     = (const int*)  d_in[1];
    const float* W_l0   = (const float*)d_in[2];
    const float* b_l0   = (const float*)d_in[3];
    const float* W_r0   = (const float*)d_in[4];
    const float* gamma0 = (const float*)d_in[5];
    const float* beta0  = (const float*)d_in[6];
    const float* W_l1   = (const float*)d_in[7];
    const float* b_l1   = (const float*)d_in[8];
    const float* W_r1   = (const float*)d_in[9];
    const float* gamma1 = (const float*)d_in[10];
    const float* beta1  = (const float*)d_in[11];
    float* out = (float*)d_out;

    const int edge_blocks   = (N_EDGES + 255) / 256;
    const int gemm_blocks   = (N_NODES + 127) / 128;
    const int gather_blocks = (N_NODES + 7) / 8;    // 8 nodes (warps) per block

    zero_small<<<(N_NODES + 255) / 256, 256>>>();
    csr_hist<<<edge_blocks, 256>>>(ei);
    scan_p1<<<SCAN_BLOCKS, 256>>>();
    scan_p23<<<SCAN_BLOCKS, 256>>>();
    csr_fill<<<edge_blocks, 256>>>(ei);

    // Layer 0
    gemm128<0><<<dim3(gemm_blocks, 2), 256>>>(x, W_l0, W_r0, b_l0, nullptr, nullptr);
    gather_stats<0><<<gather_blocks, 256>>>();

    // Layer 1 (BN0 affine computed in-kernel; BN0+ReLU fused into A-load)
    gemm128<1><<<dim3(gemm_blocks, 2), 256>>>(x, W_l1, W_r1, b_l1, gamma0, beta0);
    gather_stats<1><<<gather_blocks, 256>>>();
    apply_out<<<2048, 256>>>(out, gamma1, beta1);
}